// round 14
// baseline (speedup 1.0000x reference)
#include <cuda_runtime.h>
#include <math.h>

#define BN    737280      // total elements (8 * 92160)
#define BNH   368640      // BN / 2 (k1 ILP split)
#define NPIX  92160       // elements per (b,t) slice
#define NTRK  512
#define NSEG  4096        // 8 * 512
#define NCH   66
#define WCH   68          // wsum/srow row stride (16B-aligned)
#define REPL  4           // accumulator replicas (contention spreading)
#define THR   2.0f
#define DKS   0.05f

// k3 smem layout strides (bank-conflict padding)
#define CSR   69          // cache row stride (odd-ish vs 32 banks)
#define SSR   67          // stage row stride
#define K3_SMEM ((512 * CSR + 256 * SSR + 512) * 4)

// ---------------- scratch (device globals; no allocation) ----------------
struct Scratch {
    int    cnt[REPL * NSEG];
    float4 p1[REPL * NSEG];              // {z1, wx, wy, wz}
    float  wsum[REPL * NSEG * WCH];      // [0..65]=w*ch, [66]=z2
};
__device__ __align__(16) Scratch        g_s;
__device__ unsigned long long           g_repkey[REPL * NSEG];  // (~fok(k0))<<32 | idx
__device__ __align__(16) float          g_srow[NSEG * WCH];     // finalized segment row
__device__ int                          g_rep[NSEG];
__device__ unsigned char                g_flags[BN];

// ordered-uint mapping for floats (bijective, order-preserving)
__device__ __forceinline__ unsigned fok(float f) {
    unsigned b = __float_as_uint(f);
    return (b & 0x80000000u) ? ~b : (b | 0x80000000u);
}
__device__ __forceinline__ float kof(unsigned u) {
    unsigned b = (u & 0x80000000u) ? (u & 0x7FFFFFFFu) : ~u;
    return __uint_as_float(b);
}
__device__ __forceinline__ int seg_of(int i, int g) {
    return (i / NPIX) * NTRK + g;
}
__device__ __forceinline__ void red_add_v4(float* p, float a, float b, float c, float d) {
    asm volatile("red.global.add.v4.f32 [%0], {%1, %2, %3, %4};"
                 :: "l"(p), "f"(a), "f"(b), "f"(c), "f"(d) : "memory");
}

// load all 66 channels for element i into buf (k2 only)
__device__ __forceinline__ void load_row(
    int i, float* buf,
    const float* __restrict__ cen, const float* __restrict__ off,
    const float* __restrict__ opa, const float* __restrict__ sca,
    const float* __restrict__ rot, const float* __restrict__ fdc,
    const float* __restrict__ kp,  const float* __restrict__ ins,
    const float* __restrict__ mot) {
    #pragma unroll
    for (int c = 0; c < 3; c++) buf[c]      = cen[3 * i + c];
    #pragma unroll
    for (int c = 0; c < 3; c++) buf[3 + c]  = off[3 * i + c];
    buf[6] = opa[i];
    #pragma unroll
    for (int c = 0; c < 3; c++) buf[7 + c]  = sca[3 * i + c];
    {
        float4 r4 = reinterpret_cast<const float4*>(rot)[i];
        buf[10] = r4.x; buf[11] = r4.y; buf[12] = r4.z; buf[13] = r4.w;
    }
    #pragma unroll
    for (int c = 0; c < 3; c++) buf[14 + c] = fdc[3 * i + c];
    buf[17] = kp[i];
    const float4* ip = reinterpret_cast<const float4*>(ins) + (size_t)i * 8;
    #pragma unroll
    for (int q = 0; q < 8; q++) {
        float4 v = ip[q];
        buf[18 + 4 * q + 0] = v.x; buf[18 + 4 * q + 1] = v.y;
        buf[18 + 4 * q + 2] = v.z; buf[18 + 4 * q + 3] = v.w;
    }
    const float4* mp = reinterpret_cast<const float4*>(mot) + (size_t)i * 4;
    #pragma unroll
    for (int q = 0; q < 4; q++) {
        float4 v = mp[q];
        buf[50 + 4 * q + 0] = v.x; buf[50 + 4 * q + 1] = v.y;
        buf[50 + 4 * q + 2] = v.z; buf[50 + 4 * q + 3] = v.w;
    }
}

// ---------------- kernels ----------------
// count + phase-1 softmax sums into per-replica accumulators (2 elems/thread)
__global__ void __launch_bounds__(256)
k1(const float* __restrict__ cen, const float* __restrict__ kp,
   const int* __restrict__ gid) {
    int t = blockIdx.x * blockDim.x + threadIdx.x;
    int rbase = (blockIdx.x & (REPL - 1)) * NSEG;
    #pragma unroll
    for (int h = 0; h < 2; h++) {
        int i = t + h * BNH;
        int g = gid[i];
        if (g >= 0) {
            int s = seg_of(i, g) + rbase;
            atomicAdd(&g_s.cnt[s], 1);
            float e = __expf(kp[i]);
            red_add_v4(&g_s.p1[s].x, e,
                       e * cen[3 * i + 0], e * cen[3 * i + 1], e * cen[3 * i + 2]);
        }
    }
}

// activity + weighted accumulation (per-replica) + representative key.
__global__ void __launch_bounds__(256)
k2(const float* __restrict__ cen, const float* __restrict__ off,
   const float* __restrict__ opa, const float* __restrict__ sca,
   const float* __restrict__ rot, const float* __restrict__ fdc,
   const float* __restrict__ kp,  const float* __restrict__ ins,
   const float* __restrict__ mot, const int* __restrict__ gid) {
    int i = blockIdx.x * blockDim.x + threadIdx.x;
    if (i >= BN) return;
    int g = gid[i];
    int s = 0;
    unsigned char f = 0;
    float k0 = 0.0f;
    if (g >= 0) {
        s = seg_of(i, g);
        int cnt = 0;
        float z1 = 0.f, wx = 0.f, wy = 0.f, wz = 0.f;
        #pragma unroll
        for (int r = 0; r < REPL; r++) {
            cnt += __ldg(&g_s.cnt[r * NSEG + s]);
            float4 p = __ldg(&g_s.p1[r * NSEG + s]);
            z1 += p.x; wx += p.y; wy += p.z; wz += p.w;
        }
        if (cnt >= 2) {
            float zinv = 1.0f / fmaxf(z1, 1e-20f);
            float dx = cen[3 * i + 0] - wx * zinv;
            float dy = cen[3 * i + 1] - wy * zinv;
            float dz = cen[3 * i + 2] - wz * zinv;
            if (sqrtf(dx * dx + dy * dy + dz * dz) <= THR) {
                f = 1;
                k0 = kp[i];
            }
        }
    }
    g_flags[i] = f;
    if (!f) return;

    float buf[NCH];
    load_row(i, buf, cen, off, opa, sca, rot, fdc, kp, ins, mot);
    float e = __expf(k0);
    int sr = s + (blockIdx.x & (REPL - 1)) * NSEG;
    float* ws = &g_s.wsum[(size_t)sr * WCH];
    #pragma unroll
    for (int q = 0; q < 16; q++)
        red_add_v4(ws + 4 * q,
                   e * buf[4 * q + 0], e * buf[4 * q + 1],
                   e * buf[4 * q + 2], e * buf[4 * q + 3]);
    red_add_v4(ws + 64, e * buf[64], e * buf[65], e, 0.0f);

    unsigned long long key =
        ((unsigned long long)(~fok(k0)) << 32) | (unsigned)i;
    atomicMin(&g_repkey[sr], key);
}

// warp-per-segment finalize: collapse replicas, means, rotation norm, mkeep, rep
__global__ void __launch_bounds__(256)
k_seg() {
    const unsigned FULL = 0xFFFFFFFFu;
    int warp = (blockIdx.x * blockDim.x + threadIdx.x) >> 5;
    int lane = threadIdx.x & 31;
    if (warp >= NSEG) return;
    int s = warp;

    float a0 = 0.f, a1 = 0.f, a2 = 0.f;
    #pragma unroll
    for (int r = 0; r < REPL; r++) {
        const float* ws = &g_s.wsum[(size_t)(r * NSEG + s) * WCH];
        a0 += ws[lane];
        a1 += ws[lane + 32];
        if (lane < 4) a2 += ws[lane + 64];
    }
    float z2   = __shfl_sync(FULL, a2, 2);     // z2 = channel 66
    float zinv = 1.0f / fmaxf(z2, 1e-20f);
    a0 *= zinv; a1 *= zinv; a2 *= zinv;

    float r10 = __shfl_sync(FULL, a0, 10);
    float r11 = __shfl_sync(FULL, a0, 11);
    float r12 = __shfl_sync(FULL, a0, 12);
    float r13 = __shfl_sync(FULL, a0, 13);
    float nr  = sqrtf(r10 * r10 + r11 * r11 + r12 * r12 + r13 * r13);
    float ri  = 1.0f / fmaxf(nr, 1e-12f);
    if (lane >= 10 && lane <= 13) a0 *= ri;

    unsigned long long key = 0xFFFFFFFFFFFFFFFFull;
    if (lane == 0) {
        #pragma unroll
        for (int r = 0; r < REPL; r++) {
            unsigned long long k = g_repkey[r * NSEG + s];
            if (k < key) key = k;
        }
        g_rep[s] = (int)(unsigned)(key & 0xFFFFFFFFull);
    }
    key = __shfl_sync(FULL, key, 0);
    float m2 = kof(~(unsigned)(key >> 32));
    if (lane == 17) a0 = m2;   // mkeep = segment max keep over active

    float* r = &g_srow[(size_t)s * WCH];
    r[lane]      = a0;
    r[lane + 32] = a1;
    if (lane < 2) r[lane + 64] = a2;   // channels 64, 65
}

// output: block = 1024 elements of one slice. The slice's 512 srow rows are
// cached in smem once; quads gather from smem (no scattered global loads);
// staged rows written out fully coalesced.
__global__ void __launch_bounds__(1024, 1)
k3(const float* __restrict__ cen, const float* __restrict__ off,
   const float* __restrict__ opa, const float* __restrict__ sca,
   const float* __restrict__ rot, const float* __restrict__ fdc,
   const float* __restrict__ kp,  const float* __restrict__ ins,
   const float* __restrict__ mot, const int* __restrict__ gid,
   float* __restrict__ out) {
    extern __shared__ float sm[];
    float* cache = sm;                          // 512 * CSR
    float* stage = sm + 512 * CSR;              // 256 * SSR
    int*   repS  = (int*)(sm + 512 * CSR + 256 * SSR);  // 512

    int tid    = threadIdx.x;
    int blk    = blockIdx.x;
    int slice  = blk / 90;                      // 90 blocks per slice
    int base_i = blk * 1024;
    int segb   = slice * NTRK;

    // cooperative load of the slice's srow table (coalesced global reads)
    const float* src = &g_srow[(size_t)segb * WCH];
    for (int idx = tid; idx < 512 * WCH; idx += 1024) {
        int r = idx / WCH;
        int c = idx - r * WCH;
        cache[r * CSR + c] = src[idx];
    }
    if (tid < 512) repS[tid] = g_rep[segb + tid];
    __syncthreads();

    int e = tid >> 2;        // element slot within wave (0..255)
    int j = tid & 3;         // quad lane: channels [LO[j], HI[j])
    const int LO = (j == 0) ? 0 : (j == 1) ? 17 : (j == 2) ? 33 : 50;
    const int HI = (j == 0) ? 17 : (j == 1) ? 33 : (j == 2) ? 50 : 66;

    #pragma unroll 1
    for (int w = 0; w < 4; w++) {
        int i = base_i + w * 256 + e;
        float* st = &stage[e * SSR];
        if (g_flags[i]) {
            int g = gid[i];
            const float* cr = &cache[g * CSR];
            float sfac = (i == repS[g]) ? 1.0f : DKS;
            for (int c = LO; c < HI; c++) {
                float v = cr[c];
                if (c == 6 || c == 17) v *= sfac;
                st[c] = v;
            }
        } else {
            if (j == 0) {        // channels 0..16
                st[0] = cen[3 * i]; st[1] = cen[3 * i + 1]; st[2] = cen[3 * i + 2];
                st[3] = off[3 * i]; st[4] = off[3 * i + 1]; st[5] = off[3 * i + 2];
                st[6] = opa[i];
                st[7] = sca[3 * i]; st[8] = sca[3 * i + 1]; st[9] = sca[3 * i + 2];
                float4 rv = reinterpret_cast<const float4*>(rot)[i];
                st[10] = rv.x; st[11] = rv.y; st[12] = rv.z; st[13] = rv.w;
                st[14] = fdc[3 * i]; st[15] = fdc[3 * i + 1]; st[16] = fdc[3 * i + 2];
            } else if (j == 1) { // channels 17..32 : kp + ins[0..14]
                st[17] = kp[i];
                const float* ip = ins + (size_t)i * 32;
                #pragma unroll
                for (int c = 0; c < 15; c++) st[18 + c] = ip[c];
            } else if (j == 2) { // channels 33..49 : ins[15..31]
                const float* ip = ins + (size_t)i * 32;
                #pragma unroll
                for (int c = 15; c < 32; c++) st[18 + c] = ip[c];
            } else {             // channels 50..65 : mot[0..15]
                const float4* mp = reinterpret_cast<const float4*>(mot) + (size_t)i * 4;
                #pragma unroll
                for (int q = 0; q < 4; q++) {
                    float4 v = mp[q];
                    st[50 + 4 * q + 0] = v.x; st[50 + 4 * q + 1] = v.y;
                    st[50 + 4 * q + 2] = v.z; st[50 + 4 * q + 3] = v.w;
                }
            }
        }
        __syncthreads();

        // coalesced write: 256 rows x 66 ch = 4224 float4
        float4* dst = reinterpret_cast<float4*>(out + (size_t)(base_i + w * 256) * NCH);
        for (int f4 = tid; f4 < (256 * NCH) / 4; f4 += 1024) {
            int f   = 4 * f4;
            int row = f / NCH;
            int c   = f - row * NCH;     // even: 0,2,...,64
            const float* sp = &stage[row * SSR + c];
            float4 v;
            if (c <= 62) {
                v.x = sp[0]; v.y = sp[1]; v.z = sp[2]; v.w = sp[3];
            } else {                     // c == 64: spans into next stage row
                const float* sp2 = &stage[(row + 1) * SSR];
                v.x = sp[0]; v.y = sp[1]; v.z = sp2[0]; v.w = sp2[1];
            }
            dst[f4] = v;
        }
        __syncthreads();
    }
}

// ---------------- launcher ----------------
extern "C" void kernel_launch(void* const* d_in, const int* in_sizes, int n_in,
                              void* d_out, int out_size) {
    const float* cen = (const float*)d_in[0];
    const float* off = (const float*)d_in[1];
    const float* opa = (const float*)d_in[2];
    const float* sca = (const float*)d_in[3];
    const float* rot = (const float*)d_in[4];
    const float* fdc = (const float*)d_in[5];
    const float* kp  = (const float*)d_in[6];
    const float* ins = (const float*)d_in[7];
    const float* mot = (const float*)d_in[8];
    const int*   gid = (const int*)d_in[9];
    float* out = (float*)d_out;

    void *p_s, *p_key;
    cudaGetSymbolAddress(&p_s,   g_s);
    cudaGetSymbolAddress(&p_key, g_repkey);
    cudaMemsetAsync(p_s,   0,    sizeof(Scratch));
    cudaMemsetAsync(p_key, 0xFF, (size_t)REPL * NSEG * sizeof(unsigned long long));

    cudaFuncSetAttribute(k3, cudaFuncAttributeMaxDynamicSharedMemorySize, K3_SMEM);

    const int TB = 256;
    k1   <<<BNH / TB, TB>>>(cen, kp, gid);
    k2   <<<BN / TB, TB>>>(cen, off, opa, sca, rot, fdc, kp, ins, mot, gid);
    k_seg<<<(NSEG * 32) / TB, TB>>>();
    k3   <<<BN / 1024, 1024, K3_SMEM>>>(cen, off, opa, sca, rot, fdc, kp, ins, mot, gid, out);
}

// round 15
// speedup vs baseline: 1.2635x; 1.2635x over previous
#include <cuda_runtime.h>
#include <math.h>

#define BN    737280      // total elements (8 * 92160)
#define BNH   368640      // BN / 2 (k1 ILP split)
#define NPIX  92160       // elements per (b,t) slice
#define NTRK  512
#define NSEG  4096        // 8 * 512
#define NCH   66
#define WCH   68          // wsum/srow row stride (16B-aligned)
#define REPL  4           // accumulator replicas (contention spreading)
#define THR   2.0f
#define DKS   0.05f

// ---------------- scratch (device globals; no allocation) ----------------
struct Scratch {
    int    cnt[REPL * NSEG];
    float4 p1[REPL * NSEG];              // {z1, wx, wy, wz}
    float  wsum[REPL * NSEG * WCH];      // [0..65]=w*ch, [66]=z2
};
__device__ __align__(16) Scratch        g_s;
__device__ unsigned long long           g_repkey[REPL * NSEG];  // (~fok(k0))<<32 | idx
__device__ __align__(16) float          g_srow[NSEG * WCH];     // finalized segment row
__device__ int                          g_rep[NSEG];
__device__ unsigned char                g_flags[BN];

// ordered-uint mapping for floats (bijective, order-preserving)
__device__ __forceinline__ unsigned fok(float f) {
    unsigned b = __float_as_uint(f);
    return (b & 0x80000000u) ? ~b : (b | 0x80000000u);
}
__device__ __forceinline__ float kof(unsigned u) {
    unsigned b = (u & 0x80000000u) ? (u & 0x7FFFFFFFu) : ~u;
    return __uint_as_float(b);
}
__device__ __forceinline__ int seg_of(int i, int g) {
    return (i / NPIX) * NTRK + g;
}
__device__ __forceinline__ void red_add_v4(float* p, float a, float b, float c, float d) {
    asm volatile("red.global.add.v4.f32 [%0], {%1, %2, %3, %4};"
                 :: "l"(p), "f"(a), "f"(b), "f"(c), "f"(d) : "memory");
}

// activity predicate — __noinline__ so BOTH k23 roles execute the identical
// SASS (bit-identical float sequence -> identical flags)
__device__ __noinline__ int compute_active(int i, int g,
    const float* __restrict__ cen, const float* __restrict__ kp) {
    if (g < 0) return 0;
    int s = seg_of(i, g);
    int cnt = 0;
    float z1 = 0.f, wx = 0.f, wy = 0.f, wz = 0.f;
    #pragma unroll
    for (int r = 0; r < REPL; r++) {
        cnt += __ldg(&g_s.cnt[r * NSEG + s]);
        float4 p = __ldg(&g_s.p1[r * NSEG + s]);
        z1 += p.x; wx += p.y; wy += p.z; wz += p.w;
    }
    if (cnt < 2) return 0;
    float zinv = 1.0f / fmaxf(z1, 1e-20f);
    float dx = cen[3 * i + 0] - wx * zinv;
    float dy = cen[3 * i + 1] - wy * zinv;
    float dz = cen[3 * i + 2] - wz * zinv;
    return sqrtf(dx * dx + dy * dy + dz * dz) <= THR;
}

// load all 66 channels for element i into buf (k23 role A)
__device__ __forceinline__ void load_row(
    int i, float* buf,
    const float* __restrict__ cen, const float* __restrict__ off,
    const float* __restrict__ opa, const float* __restrict__ sca,
    const float* __restrict__ rot, const float* __restrict__ fdc,
    const float* __restrict__ kp,  const float* __restrict__ ins,
    const float* __restrict__ mot) {
    #pragma unroll
    for (int c = 0; c < 3; c++) buf[c]      = cen[3 * i + c];
    #pragma unroll
    for (int c = 0; c < 3; c++) buf[3 + c]  = off[3 * i + c];
    buf[6] = opa[i];
    #pragma unroll
    for (int c = 0; c < 3; c++) buf[7 + c]  = sca[3 * i + c];
    {
        float4 r4 = reinterpret_cast<const float4*>(rot)[i];
        buf[10] = r4.x; buf[11] = r4.y; buf[12] = r4.z; buf[13] = r4.w;
    }
    #pragma unroll
    for (int c = 0; c < 3; c++) buf[14 + c] = fdc[3 * i + c];
    buf[17] = kp[i];
    const float4* ip = reinterpret_cast<const float4*>(ins) + (size_t)i * 8;
    #pragma unroll
    for (int q = 0; q < 8; q++) {
        float4 v = ip[q];
        buf[18 + 4 * q + 0] = v.x; buf[18 + 4 * q + 1] = v.y;
        buf[18 + 4 * q + 2] = v.z; buf[18 + 4 * q + 3] = v.w;
    }
    const float4* mp = reinterpret_cast<const float4*>(mot) + (size_t)i * 4;
    #pragma unroll
    for (int q = 0; q < 4; q++) {
        float4 v = mp[q];
        buf[50 + 4 * q + 0] = v.x; buf[50 + 4 * q + 1] = v.y;
        buf[50 + 4 * q + 2] = v.z; buf[50 + 4 * q + 3] = v.w;
    }
}

// ---------------- kernels ----------------
// count + phase-1 softmax sums into per-replica accumulators (2 elems/thread)
__global__ void __launch_bounds__(256)
k1(const float* __restrict__ cen, const float* __restrict__ kp,
   const int* __restrict__ gid) {
    int t = blockIdx.x * blockDim.x + threadIdx.x;
    int rbase = (blockIdx.x & (REPL - 1)) * NSEG;
    #pragma unroll
    for (int h = 0; h < 2; h++) {
        int i = t + h * BNH;
        int g = gid[i];
        if (g >= 0) {
            int s = seg_of(i, g) + rbase;
            atomicAdd(&g_s.cnt[s], 1);
            float e = __expf(kp[i]);
            red_add_v4(&g_s.p1[s].x, e,
                       e * cen[3 * i + 0], e * cen[3 * i + 1], e * cen[3 * i + 2]);
        }
    }
}

// fused kernel, two block roles interleaved by parity for SM co-residency:
//   role A (even bid): activity + weighted atomic accumulation (LTS-bound)
//   role B (odd bid):  inactive/invalid raw-row passthrough (L1/DRAM-bound)
// Both depend only on k1; complementary pipes overlap.
__global__ void __launch_bounds__(256)
k23(const float* __restrict__ cen, const float* __restrict__ off,
    const float* __restrict__ opa, const float* __restrict__ sca,
    const float* __restrict__ rot, const float* __restrict__ fdc,
    const float* __restrict__ kp,  const float* __restrict__ ins,
    const float* __restrict__ mot, const int* __restrict__ gid,
    float* __restrict__ out) {
    int vb = blockIdx.x >> 1;
    int i  = vb * 256 + threadIdx.x;
    int g  = gid[i];
    int f  = compute_active(i, g, cen, kp);

    if ((blockIdx.x & 1) == 0) {
        // ---- role A: flags + atomic accumulation ----
        g_flags[i] = (unsigned char)f;
        if (!f) return;
        int s = seg_of(i, g);
        float k0 = kp[i];
        float buf[NCH];
        load_row(i, buf, cen, off, opa, sca, rot, fdc, kp, ins, mot);
        float e = __expf(k0);
        int sr = s + (vb & (REPL - 1)) * NSEG;
        float* ws = &g_s.wsum[(size_t)sr * WCH];
        #pragma unroll
        for (int q = 0; q < 16; q++)
            red_add_v4(ws + 4 * q,
                       e * buf[4 * q + 0], e * buf[4 * q + 1],
                       e * buf[4 * q + 2], e * buf[4 * q + 3]);
        red_add_v4(ws + 64, e * buf[64], e * buf[65], e, 0.0f);
        unsigned long long key =
            ((unsigned long long)(~fok(k0)) << 32) | (unsigned)i;
        atomicMin(&g_repkey[sr], key);
    } else {
        // ---- role B: passthrough of inactive/invalid rows (streaming float2) ----
        if (f) return;
        float2* o2 = reinterpret_cast<float2*>(out + (size_t)i * NCH);
        o2[0] = make_float2(cen[3 * i],     cen[3 * i + 1]);
        o2[1] = make_float2(cen[3 * i + 2], off[3 * i]);
        o2[2] = make_float2(off[3 * i + 1], off[3 * i + 2]);
        o2[3] = make_float2(opa[i],         sca[3 * i]);
        o2[4] = make_float2(sca[3 * i + 1], sca[3 * i + 2]);
        float4 rv = reinterpret_cast<const float4*>(rot)[i];
        o2[5] = make_float2(rv.x, rv.y);
        o2[6] = make_float2(rv.z, rv.w);
        o2[7] = make_float2(fdc[3 * i],     fdc[3 * i + 1]);
        o2[8] = make_float2(fdc[3 * i + 2], kp[i]);
        const float4* ip = reinterpret_cast<const float4*>(ins) + (size_t)i * 8;
        #pragma unroll
        for (int q = 0; q < 8; q++) {
            float4 v = ip[q];
            o2[9  + 2 * q] = make_float2(v.x, v.y);
            o2[10 + 2 * q] = make_float2(v.z, v.w);
        }
        const float4* mp = reinterpret_cast<const float4*>(mot) + (size_t)i * 4;
        #pragma unroll
        for (int q = 0; q < 4; q++) {
            float4 v = mp[q];
            o2[25 + 2 * q] = make_float2(v.x, v.y);
            o2[26 + 2 * q] = make_float2(v.z, v.w);
        }
    }
}

// warp-per-segment finalize: collapse replicas, means, rotation norm, mkeep, rep
__global__ void __launch_bounds__(256)
k_seg() {
    const unsigned FULL = 0xFFFFFFFFu;
    int warp = (blockIdx.x * blockDim.x + threadIdx.x) >> 5;
    int lane = threadIdx.x & 31;
    if (warp >= NSEG) return;
    int s = warp;

    float a0 = 0.f, a1 = 0.f, a2 = 0.f;
    #pragma unroll
    for (int r = 0; r < REPL; r++) {
        const float* ws = &g_s.wsum[(size_t)(r * NSEG + s) * WCH];
        a0 += ws[lane];
        a1 += ws[lane + 32];
        if (lane < 4) a2 += ws[lane + 64];
    }
    float z2   = __shfl_sync(FULL, a2, 2);     // z2 = channel 66
    float zinv = 1.0f / fmaxf(z2, 1e-20f);
    a0 *= zinv; a1 *= zinv; a2 *= zinv;

    float r10 = __shfl_sync(FULL, a0, 10);
    float r11 = __shfl_sync(FULL, a0, 11);
    float r12 = __shfl_sync(FULL, a0, 12);
    float r13 = __shfl_sync(FULL, a0, 13);
    float nr  = sqrtf(r10 * r10 + r11 * r11 + r12 * r12 + r13 * r13);
    float ri  = 1.0f / fmaxf(nr, 1e-12f);
    if (lane >= 10 && lane <= 13) a0 *= ri;

    unsigned long long key = 0xFFFFFFFFFFFFFFFFull;
    if (lane == 0) {
        #pragma unroll
        for (int r = 0; r < REPL; r++) {
            unsigned long long k = g_repkey[r * NSEG + s];
            if (k < key) key = k;
        }
        g_rep[s] = (int)(unsigned)(key & 0xFFFFFFFFull);
    }
    key = __shfl_sync(FULL, key, 0);
    float m2 = kof(~(unsigned)(key >> 32));
    if (lane == 17) a0 = m2;   // mkeep = segment max keep over active

    float* r = &g_srow[(size_t)s * WCH];
    r[lane]      = a0;
    r[lane + 32] = a1;
    if (lane < 2) r[lane + 64] = a2;   // channels 64, 65
}

// active rows only: gather finalized segment row into smem stage (float4),
// then row-predicated coalesced float2 writes (no row straddle).
__global__ void __launch_bounds__(128)
k3a(const int* __restrict__ gid, float* __restrict__ out) {
    __shared__ float stage[128 * WCH];       // 34,816 B
    __shared__ int   sflag[128];
    int tid = threadIdx.x;
    int i = blockIdx.x * 128 + tid;

    int f = g_flags[i];
    sflag[tid] = f;
    if (f) {
        int s = seg_of(i, gid[i]);
        float sfac = (i == g_rep[s]) ? 1.0f : DKS;
        const float4* r4 = reinterpret_cast<const float4*>(&g_srow[(size_t)s * WCH]);
        float* st = &stage[tid * WCH];
        #pragma unroll
        for (int q = 0; q < 17; q++) {
            float4 v = __ldg(r4 + q);
            if (q == 1) v.z *= sfac;     // channel 6 (opacity)
            if (q == 4) v.y *= sfac;     // channel 17 (keep)
            *reinterpret_cast<float4*>(st + 4 * q) = v;
        }
    }
    __syncthreads();

    // 128 rows x 33 float2 each; float2 never straddles a row (66 = 2*33)
    float2* dst = reinterpret_cast<float2*>(out + (size_t)blockIdx.x * 128 * NCH);
    #pragma unroll 1
    for (int f2 = tid; f2 < 128 * 33; f2 += 128) {
        int row = f2 / 33;
        int c2  = f2 - row * 33;
        if (sflag[row])
            dst[f2] = *reinterpret_cast<const float2*>(&stage[row * WCH + 2 * c2]);
    }
}

// ---------------- launcher ----------------
extern "C" void kernel_launch(void* const* d_in, const int* in_sizes, int n_in,
                              void* d_out, int out_size) {
    const float* cen = (const float*)d_in[0];
    const float* off = (const float*)d_in[1];
    const float* opa = (const float*)d_in[2];
    const float* sca = (const float*)d_in[3];
    const float* rot = (const float*)d_in[4];
    const float* fdc = (const float*)d_in[5];
    const float* kp  = (const float*)d_in[6];
    const float* ins = (const float*)d_in[7];
    const float* mot = (const float*)d_in[8];
    const int*   gid = (const int*)d_in[9];
    float* out = (float*)d_out;

    void *p_s, *p_key;
    cudaGetSymbolAddress(&p_s,   g_s);
    cudaGetSymbolAddress(&p_key, g_repkey);
    cudaMemsetAsync(p_s,   0,    sizeof(Scratch));
    cudaMemsetAsync(p_key, 0xFF, (size_t)REPL * NSEG * sizeof(unsigned long long));

    const int TB = 256;
    k1   <<<BNH / TB, TB>>>(cen, kp, gid);
    k23  <<<2 * (BN / TB), TB>>>(cen, off, opa, sca, rot, fdc, kp, ins, mot, gid, out);
    k_seg<<<(NSEG * 32) / TB, TB>>>();
    k3a  <<<BN / 128, 128>>>(gid, out);
}

// round 17
// speedup vs baseline: 1.3415x; 1.0617x over previous
#include <cuda_runtime.h>
#include <math.h>

#define BN    737280      // total elements (8 * 92160)
#define BNQ   184320      // BN / 4 (k1 ILP split)
#define NPIX  92160       // elements per (b,t) slice
#define NTRK  512
#define NSEG  4096        // 8 * 512
#define NCH   66
#define WCH   68          // wsum/srow accumulator row stride (16B-aligned)
#define SST   67          // k3 stage stride: 67 mod 32 = 3 -> conflict-free
#define REPL  4           // accumulator replicas (contention spreading)
#define THR   2.0f
#define DKS   0.05f

// ---------------- scratch (device globals; no allocation) ----------------
struct Scratch {
    int    cnt[REPL * NSEG];
    float4 p1[REPL * NSEG];              // {z1, wx, wy, wz}
    float  wsum[REPL * NSEG * WCH];      // [0..65]=w*ch, [66]=z2
};
__device__ __align__(16) Scratch        g_s;
__device__ unsigned long long           g_repkey[REPL * NSEG];  // (~fok(k0))<<32 | idx
__device__ __align__(16) float          g_srow[NSEG * WCH];     // finalized segment row
__device__ int                          g_rep[NSEG];
__device__ unsigned char                g_flags[BN];

// ordered-uint mapping for floats (bijective, order-preserving)
__device__ __forceinline__ unsigned fok(float f) {
    unsigned b = __float_as_uint(f);
    return (b & 0x80000000u) ? ~b : (b | 0x80000000u);
}
__device__ __forceinline__ float kof(unsigned u) {
    unsigned b = (u & 0x80000000u) ? (u & 0x7FFFFFFFu) : ~u;
    return __uint_as_float(b);
}
__device__ __forceinline__ int seg_of(int i, int g) {
    return (i / NPIX) * NTRK + g;
}
__device__ __forceinline__ void red_add_v4(float* p, float a, float b, float c, float d) {
    asm volatile("red.global.add.v4.f32 [%0], {%1, %2, %3, %4};"
                 :: "l"(p), "f"(a), "f"(b), "f"(c), "f"(d) : "memory");
}

// load all 66 channels for element i into buf
// order: center(0-2) offset(3-5) opacity(6) scale(7-9) rotation(10-13)
//        feat_dc(14-16) keep(17) inst(18-49) motion(50-65)
__device__ __forceinline__ void load_row(
    int i, float* buf,
    const float* __restrict__ cen, const float* __restrict__ off,
    const float* __restrict__ opa, const float* __restrict__ sca,
    const float* __restrict__ rot, const float* __restrict__ fdc,
    const float* __restrict__ kp,  const float* __restrict__ ins,
    const float* __restrict__ mot) {
    #pragma unroll
    for (int c = 0; c < 3; c++) buf[c]      = cen[3 * i + c];
    #pragma unroll
    for (int c = 0; c < 3; c++) buf[3 + c]  = off[3 * i + c];
    buf[6] = opa[i];
    #pragma unroll
    for (int c = 0; c < 3; c++) buf[7 + c]  = sca[3 * i + c];
    {
        float4 r4 = reinterpret_cast<const float4*>(rot)[i];
        buf[10] = r4.x; buf[11] = r4.y; buf[12] = r4.z; buf[13] = r4.w;
    }
    #pragma unroll
    for (int c = 0; c < 3; c++) buf[14 + c] = fdc[3 * i + c];
    buf[17] = kp[i];
    const float4* ip = reinterpret_cast<const float4*>(ins) + (size_t)i * 8;
    #pragma unroll
    for (int q = 0; q < 8; q++) {
        float4 v = ip[q];
        buf[18 + 4 * q + 0] = v.x; buf[18 + 4 * q + 1] = v.y;
        buf[18 + 4 * q + 2] = v.z; buf[18 + 4 * q + 3] = v.w;
    }
    const float4* mp = reinterpret_cast<const float4*>(mot) + (size_t)i * 4;
    #pragma unroll
    for (int q = 0; q < 4; q++) {
        float4 v = mp[q];
        buf[50 + 4 * q + 0] = v.x; buf[50 + 4 * q + 1] = v.y;
        buf[50 + 4 * q + 2] = v.z; buf[50 + 4 * q + 3] = v.w;
    }
}

// ---------------- kernels ----------------
// count + phase-1 softmax sums into per-replica accumulators (4 elems/thread)
__global__ void __launch_bounds__(256)
k1(const float* __restrict__ cen, const float* __restrict__ kp,
   const int* __restrict__ gid) {
    int t = blockIdx.x * blockDim.x + threadIdx.x;
    int rbase = (blockIdx.x & (REPL - 1)) * NSEG;
    #pragma unroll
    for (int h = 0; h < 4; h++) {
        int i = t + h * BNQ;
        int g = gid[i];
        if (g >= 0) {
            int s = seg_of(i, g) + rbase;
            atomicAdd(&g_s.cnt[s], 1);
            float e = __expf(kp[i]);
            red_add_v4(&g_s.p1[s].x, e,
                       e * cen[3 * i + 0], e * cen[3 * i + 1], e * cen[3 * i + 2]);
        }
    }
}

// activity + weighted accumulation (per-replica) + representative key.
// Phase-1 replicas are summed inline (L1/L2-resident table).
__global__ void __launch_bounds__(256)
k2(const float* __restrict__ cen, const float* __restrict__ off,
   const float* __restrict__ opa, const float* __restrict__ sca,
   const float* __restrict__ rot, const float* __restrict__ fdc,
   const float* __restrict__ kp,  const float* __restrict__ ins,
   const float* __restrict__ mot, const int* __restrict__ gid) {
    int i = blockIdx.x * blockDim.x + threadIdx.x;
    if (i >= BN) return;
    int g = gid[i];
    int s = 0;
    unsigned char f = 0;
    float k0 = 0.0f;
    if (g >= 0) {
        s = seg_of(i, g);
        int cnt = 0;
        float z1 = 0.f, wx = 0.f, wy = 0.f, wz = 0.f;
        #pragma unroll
        for (int r = 0; r < REPL; r++) {
            cnt += __ldg(&g_s.cnt[r * NSEG + s]);
            float4 p = __ldg(&g_s.p1[r * NSEG + s]);
            z1 += p.x; wx += p.y; wy += p.z; wz += p.w;
        }
        if (cnt >= 2) {
            float zinv = 1.0f / fmaxf(z1, 1e-20f);
            float dx = cen[3 * i + 0] - wx * zinv;
            float dy = cen[3 * i + 1] - wy * zinv;
            float dz = cen[3 * i + 2] - wz * zinv;
            if (sqrtf(dx * dx + dy * dy + dz * dz) <= THR) {
                f = 1;
                k0 = kp[i];
            }
        }
    }
    g_flags[i] = f;
    if (!f) return;

    float buf[NCH];
    load_row(i, buf, cen, off, opa, sca, rot, fdc, kp, ins, mot);
    float e = __expf(k0);
    int sr = s + (blockIdx.x & (REPL - 1)) * NSEG;
    float* ws = &g_s.wsum[(size_t)sr * WCH];
    #pragma unroll
    for (int q = 0; q < 16; q++)
        red_add_v4(ws + 4 * q,
                   e * buf[4 * q + 0], e * buf[4 * q + 1],
                   e * buf[4 * q + 2], e * buf[4 * q + 3]);
    red_add_v4(ws + 64, e * buf[64], e * buf[65], e, 0.0f);

    unsigned long long key =
        ((unsigned long long)(~fok(k0)) << 32) | (unsigned)i;
    atomicMin(&g_repkey[sr], key);
}

// warp-per-segment finalize: collapse replicas, means, rotation norm, mkeep, rep
__global__ void __launch_bounds__(256)
k_seg() {
    const unsigned FULL = 0xFFFFFFFFu;
    int warp = (blockIdx.x * blockDim.x + threadIdx.x) >> 5;
    int lane = threadIdx.x & 31;
    if (warp >= NSEG) return;
    int s = warp;

    float a0 = 0.f, a1 = 0.f, a2 = 0.f;
    #pragma unroll
    for (int r = 0; r < REPL; r++) {
        const float* ws = &g_s.wsum[(size_t)(r * NSEG + s) * WCH];
        a0 += ws[lane];
        a1 += ws[lane + 32];
        if (lane < 4) a2 += ws[lane + 64];
    }
    float z2   = __shfl_sync(FULL, a2, 2);     // z2 = channel 66
    float zinv = 1.0f / fmaxf(z2, 1e-20f);
    a0 *= zinv; a1 *= zinv; a2 *= zinv;

    float r10 = __shfl_sync(FULL, a0, 10);
    float r11 = __shfl_sync(FULL, a0, 11);
    float r12 = __shfl_sync(FULL, a0, 12);
    float r13 = __shfl_sync(FULL, a0, 13);
    float nr  = sqrtf(r10 * r10 + r11 * r11 + r12 * r12 + r13 * r13);
    float ri  = 1.0f / fmaxf(nr, 1e-12f);
    if (lane >= 10 && lane <= 13) a0 *= ri;

    unsigned long long key = 0xFFFFFFFFFFFFFFFFull;
    if (lane == 0) {
        #pragma unroll
        for (int r = 0; r < REPL; r++) {
            unsigned long long k = g_repkey[r * NSEG + s];
            if (k < key) key = k;
        }
        g_rep[s] = (int)(unsigned)(key & 0xFFFFFFFFull);
    }
    key = __shfl_sync(FULL, key, 0);
    float m2 = kof(~(unsigned)(key >> 32));
    if (lane == 17) a0 = m2;   // mkeep = segment max keep over active

    float* r = &g_srow[(size_t)s * WCH];
    r[lane]      = a0;
    r[lane + 32] = a1;
    if (lane < 2) r[lane + 64] = a2;   // channels 64, 65
}

// output: gather (segment row for active, raw channels for inactive),
// stage in smem (stride 67 = conflict-free, all-scalar access),
// write fully coalesced
__global__ void __launch_bounds__(128, 8)
k3(const float* __restrict__ cen, const float* __restrict__ off,
   const float* __restrict__ opa, const float* __restrict__ sca,
   const float* __restrict__ rot, const float* __restrict__ fdc,
   const float* __restrict__ kp,  const float* __restrict__ ins,
   const float* __restrict__ mot, const int* __restrict__ gid,
   float* __restrict__ out) {
    __shared__ float stage[128 * SST];   // 34,304 B
    int tid = threadIdx.x;
    int i = blockIdx.x * 128 + tid;

    float* st = &stage[tid * SST];
    float buf[NCH];
    if (g_flags[i]) {
        int s = seg_of(i, gid[i]);
        float sfac = (i == g_rep[s]) ? 1.0f : DKS;
        const float4* r4 = reinterpret_cast<const float4*>(&g_srow[(size_t)s * WCH]);
        #pragma unroll
        for (int q = 0; q < 16; q++) {
            float4 v = __ldg(r4 + q);
            buf[4 * q + 0] = v.x; buf[4 * q + 1] = v.y;
            buf[4 * q + 2] = v.z; buf[4 * q + 3] = v.w;
        }
        {
            float4 v = __ldg(r4 + 16);   // channels 64,65 (+ z2, pad)
            buf[64] = v.x; buf[65] = v.y;
        }
        buf[6]  *= sfac;
        buf[17] *= sfac;
    } else {
        load_row(i, buf, cen, off, opa, sca, rot, fdc, kp, ins, mot);
    }
    #pragma unroll
    for (int c = 0; c < NCH; c++) st[c] = buf[c];   // scalar STS, conflict-free
    __syncthreads();

    // coalesced write: 128 rows x 66 ch = 2112 float4 (repack stride 67 -> 66)
    float4* dst = reinterpret_cast<float4*>(out + (size_t)blockIdx.x * 128 * NCH);
    for (int f4 = tid; f4 < (128 * NCH) / 4; f4 += 128) {
        int f   = 4 * f4;
        int row = f / NCH;
        int c   = f - row * NCH;        // even: 0,2,...,64
        const float* sp = &stage[row * SST + c];
        float4 v;
        if (c <= 62) {
            v.x = sp[0]; v.y = sp[1]; v.z = sp[2]; v.w = sp[3];
        } else {                        // c == 64: spans into next stage row
            const float* sp2 = &stage[(row + 1) * SST];
            v.x = sp[0]; v.y = sp[1]; v.z = sp2[0]; v.w = sp2[1];
        }
        dst[f4] = v;
    }
}

// ---------------- launcher ----------------
extern "C" void kernel_launch(void* const* d_in, const int* in_sizes, int n_in,
                              void* d_out, int out_size) {
    const float* cen = (const float*)d_in[0];
    const float* off = (const float*)d_in[1];
    const float* opa = (const float*)d_in[2];
    const float* sca = (const float*)d_in[3];
    const float* rot = (const float*)d_in[4];
    const float* fdc = (const float*)d_in[5];
    const float* kp  = (const float*)d_in[6];
    const float* ins = (const float*)d_in[7];
    const float* mot = (const float*)d_in[8];
    const int*   gid = (const int*)d_in[9];
    float* out = (float*)d_out;

    void *p_s, *p_key;
    cudaGetSymbolAddress(&p_s,   g_s);
    cudaGetSymbolAddress(&p_key, g_repkey);
    cudaMemsetAsync(p_s,   0,    sizeof(Scratch));
    cudaMemsetAsync(p_key, 0xFF, (size_t)REPL * NSEG * sizeof(unsigned long long));

    const int TB = 256;
    k1   <<<BNQ / TB, TB>>>(cen, kp, gid);
    k2   <<<BN / TB, TB>>>(cen, off, opa, sca, rot, fdc, kp, ins, mot, gid);
    k_seg<<<(NSEG * 32) / TB, TB>>>();
    k3   <<<BN / 128, 128>>>(cen, off, opa, sca, rot, fdc, kp, ins, mot, gid, out);
}